// round 2
// baseline (speedup 1.0000x reference)
#include <cuda_runtime.h>
#include <cuda_bf16.h>
#include <cstdint>

#define N_NODES 50000
#define N_PAD   50048           // 782 blocks * 64 rows
#define DIM     256
#define NEG     0.2f
#define LN_EPS  1e-5f
#define VS      264             // Vs row stride in floats (conflict-skewed)

// ---------------- scratch (allocation-free; __device__ globals) ----------------
__device__ unsigned char g_mask0[N_PAD];
__device__ unsigned char g_mask1[N_PAD];
__device__ unsigned char g_mask2[N_PAD];

// feat split to bf16 hi/lo, packed as (k even, k odd) bf16 pairs per uint32:
// g_f*[row*128 + k2] = pack(bf16(feat[row][2k2]), bf16(feat[row][2k2+1]))
__device__ uint32_t g_fh[(size_t)N_PAD * 128];
__device__ uint32_t g_fl[(size_t)N_PAD * 128];
// Wr split, packed column-major pairs for mma B fragments:
// g_w*[n*128 + k2] = pack(bf16(Wr[2k2][n]), bf16(Wr[2k2+1][n]))
__device__ uint32_t g_wh[256 * 128];
__device__ uint32_t g_wl[256 * 128];

// ---------------- helpers ----------------
__device__ __forceinline__ uint32_t pack_bf16(float a, float b) {
    __nv_bfloat162 h = __floats2bfloat162_rn(a, b);
    return *reinterpret_cast<uint32_t*>(&h);
}

__device__ __forceinline__ void mma16816(float c[4], const uint32_t a[4],
                                         uint32_t b0, uint32_t b1) {
    asm volatile(
        "mma.sync.aligned.m16n8k16.row.col.f32.bf16.bf16.f32 "
        "{%0,%1,%2,%3}, {%4,%5,%6,%7}, {%8,%9}, {%0,%1,%2,%3};"
        : "+f"(c[0]), "+f"(c[1]), "+f"(c[2]), "+f"(c[3])
        : "r"(a[0]), "r"(a[1]), "r"(a[2]), "r"(a[3]), "r"(b0), "r"(b1));
}

__device__ __forceinline__ float head_w(float q, float kv, float n1) {
    float x1 = q + kv;
    float z1 = fmaxf(x1, NEG * x1);
    float z0 = fmaxf(q,  NEG * q);
    float m  = fmaxf(z1, z0);
    float e1 = expf(z1 - m);
    float e0 = expf(z0 - m);
    float f1 = n1 * e1;
    return f1 / (f1 + (4.0f - n1) * e0);
}

// ---------------- prep kernels ----------------
__global__ void zero_mask_kernel(int n) {
    int i = blockIdx.x * blockDim.x + threadIdx.x;
    if (i < n) { g_mask0[i] = 0; g_mask1[i] = 0; g_mask2[i] = 0; }
}

__global__ void scatter_mask_kernel(const int* __restrict__ d0,
                                    const int* __restrict__ d1,
                                    const int* __restrict__ d2, int E) {
    int i = blockIdx.x * blockDim.x + threadIdx.x;
    if (i < E) {
        g_mask0[d0[i]] = 1;
        g_mask1[d1[i]] = 1;
        g_mask2[d2[i]] = 1;
    }
}

// Each thread converts 8 consecutive floats of one feat row (4 bf16 pairs).
__global__ void convert_feat_kernel(const float* __restrict__ feat, int n) {
    int idx = blockIdx.x * blockDim.x + threadIdx.x;
    if (idx >= N_PAD * 32) return;
    int row = idx >> 5;
    int c   = (idx & 31) << 3;          // float col base (0..248)
    float4 f0 = make_float4(0.f, 0.f, 0.f, 0.f), f1 = f0;
    if (row < n) {
        f0 = *(const float4*)&feat[(size_t)row * 256 + c];
        f1 = *(const float4*)&feat[(size_t)row * 256 + c + 4];
    }
    float x[8] = {f0.x, f0.y, f0.z, f0.w, f1.x, f1.y, f1.z, f1.w};
    uint32_t hi[4], lo[4];
    #pragma unroll
    for (int p = 0; p < 4; p++) {
        __nv_bfloat16 h0 = __float2bfloat16_rn(x[2 * p]);
        __nv_bfloat16 h1 = __float2bfloat16_rn(x[2 * p + 1]);
        float r0 = x[2 * p]     - __bfloat162float(h0);
        float r1 = x[2 * p + 1] - __bfloat162float(h1);
        hi[p] = pack_bf16(__bfloat162float(h0), __bfloat162float(h1));
        lo[p] = pack_bf16(r0, r1);
    }
    size_t o = (size_t)row * 128 + (c >> 1);
    *(uint4*)&g_fh[o] = make_uint4(hi[0], hi[1], hi[2], hi[3]);
    *(uint4*)&g_fl[o] = make_uint4(lo[0], lo[1], lo[2], lo[3]);
}

__global__ void convert_w_kernel(const float* __restrict__ Wr) {
    int idx = blockIdx.x * blockDim.x + threadIdx.x;  // over 256*128
    if (idx >= 256 * 128) return;
    int nn = idx >> 7;
    int k2 = idx & 127;
    float x0 = Wr[(size_t)(2 * k2)     * 256 + nn];
    float x1 = Wr[(size_t)(2 * k2 + 1) * 256 + nn];
    __nv_bfloat16 h0 = __float2bfloat16_rn(x0);
    __nv_bfloat16 h1 = __float2bfloat16_rn(x1);
    g_wh[idx] = pack_bf16(__bfloat162float(h0), __bfloat162float(h1));
    g_wl[idx] = pack_bf16(x0 - __bfloat162float(h0), x1 - __bfloat162float(h1));
}

// ---------------- fused HMMA GEMM + metapath epilogue ----------------
// Block: 256 threads (8 warps), tile 64 rows x 256 cols.
// Warp (wm, wn): wm = wid>>2 in {0,1} -> 32 rows; wn = wid&3 -> 64 cols.
// Per warp: 2 m-tiles x 8 n-tiles of m16n8k16, bf16x3 accumulation in fp32.
__global__ __launch_bounds__(256, 2)
void mma_gemm_epilogue(const float* __restrict__ br,
                       const float* __restrict__ rel_q,
                       const float* __restrict__ rel_k,
                       const float* __restrict__ ln_g,
                       const float* __restrict__ ln_b,
                       float* __restrict__ out, int n)
{
    extern __shared__ float Vs[];   // [64][VS]

    const int tid  = threadIdx.x;
    const int wid  = tid >> 5;
    const int lane = tid & 31;
    const int wm   = wid >> 2;
    const int wn   = wid & 3;
    const int g    = lane >> 2;
    const int t    = lane & 3;
    const int row0 = blockIdx.x * 64 + wm * 32;   // warp global row base

    float acc[2][8][4];
    #pragma unroll
    for (int mt = 0; mt < 2; mt++)
        #pragma unroll
        for (int nt = 0; nt < 8; nt++)
            #pragma unroll
            for (int q = 0; q < 4; q++) acc[mt][nt][q] = 0.0f;

    // A row pointers (k2-unit granularity)
    const uint32_t* fh0 = g_fh + (size_t)(row0 + g)      * 128;
    const uint32_t* fh1 = g_fh + (size_t)(row0 + g + 8)  * 128;
    const uint32_t* fh2 = g_fh + (size_t)(row0 + g + 16) * 128;
    const uint32_t* fh3 = g_fh + (size_t)(row0 + g + 24) * 128;
    const uint32_t* fl0 = g_fl + (size_t)(row0 + g)      * 128;
    const uint32_t* fl1 = g_fl + (size_t)(row0 + g + 8)  * 128;
    const uint32_t* fl2 = g_fl + (size_t)(row0 + g + 16) * 128;
    const uint32_t* fl3 = g_fl + (size_t)(row0 + g + 24) * 128;

    #pragma unroll 4
    for (int kc = 0; kc < 16; kc++) {
        const int kb = kc * 8;
        uint32_t ah[2][4], al[2][4];
        ah[0][0] = fh0[kb + t];     ah[0][1] = fh1[kb + t];
        ah[0][2] = fh0[kb + t + 4]; ah[0][3] = fh1[kb + t + 4];
        ah[1][0] = fh2[kb + t];     ah[1][1] = fh3[kb + t];
        ah[1][2] = fh2[kb + t + 4]; ah[1][3] = fh3[kb + t + 4];
        al[0][0] = fl0[kb + t];     al[0][1] = fl1[kb + t];
        al[0][2] = fl0[kb + t + 4]; al[0][3] = fl1[kb + t + 4];
        al[1][0] = fl2[kb + t];     al[1][1] = fl3[kb + t];
        al[1][2] = fl2[kb + t + 4]; al[1][3] = fl3[kb + t + 4];

        #pragma unroll
        for (int nt = 0; nt < 8; nt++) {
            const int nn = wn * 64 + nt * 8 + g;
            const uint32_t* wph = g_wh + nn * 128 + kb;
            const uint32_t* wpl = g_wl + nn * 128 + kb;
            uint32_t bh0 = wph[t], bh1 = wph[t + 4];
            uint32_t bl0 = wpl[t], bl1 = wpl[t + 4];
            #pragma unroll
            for (int mt = 0; mt < 2; mt++) {
                mma16816(acc[mt][nt], ah[mt], bh0, bh1);
                mma16816(acc[mt][nt], ah[mt], bl0, bl1);
                mma16816(acc[mt][nt], al[mt], bh0, bh1);
            }
        }
    }

    // ---- stage v tile to SMEM ----
    #pragma unroll
    for (int mt = 0; mt < 2; mt++) {
        #pragma unroll
        for (int nt = 0; nt < 8; nt++) {
            int rl = wm * 32 + mt * 16 + g;
            int cl = wn * 64 + nt * 8 + 2 * t;
            Vs[rl * VS + cl]           = acc[mt][nt][0];
            Vs[rl * VS + cl + 1]       = acc[mt][nt][1];
            Vs[(rl + 8) * VS + cl]     = acc[mt][nt][2];
            Vs[(rl + 8) * VS + cl + 1] = acc[mt][nt][3];
        }
    }
    __syncthreads();

    // ---- epilogue: metapath attention + ReLU + LayerNorm (validated in R1) ----
    const int tx   = lane;
    const int ty   = wid;
    const int blk0 = blockIdx.x * 64;

    const int ci = (tx & 15) * 4;
    const int ha = tx >> 4;
    const int hb = 2 + (tx >> 4);
    float rqa[4], rka[4], rqb[4], rkb[4];
    float bra[4], brb[4], ga[4], gb[4], ba[4], bb[4];
    #pragma unroll
    for (int j = 0; j < 4; j++) {
        rqa[j] = rel_q[ha * 64 + ci + j];
        rka[j] = rel_k[ha * 64 + ci + j];
        rqb[j] = rel_q[hb * 64 + ci + j];
        rkb[j] = rel_k[hb * 64 + ci + j];
        int colA = tx * 4 + j;
        int colB = 128 + tx * 4 + j;
        bra[j] = br[colA];   brb[j] = br[colB];
        ga[j]  = ln_g[colA]; gb[j]  = ln_g[colB];
        ba[j]  = ln_b[colA]; bb[j]  = ln_b[colB];
    }

    #pragma unroll
    for (int i = 0; i < 8; i++) {
        int lrow = ty * 8 + i;
        int row  = blk0 + lrow;
        if (row >= n) continue;

        float4 va = *(float4*)&Vs[lrow * VS + tx * 4];
        float4 vb = *(float4*)&Vs[lrow * VS + 128 + tx * 4];
        float vv[8];
        vv[0] = va.x + bra[0]; vv[1] = va.y + bra[1];
        vv[2] = va.z + bra[2]; vv[3] = va.w + bra[3];
        vv[4] = vb.x + brb[0]; vv[5] = vb.y + brb[1];
        vv[6] = vb.z + brb[2]; vv[7] = vb.w + brb[3];

        float pqa = 0.f, pka = 0.f, pqb = 0.f, pkb = 0.f;
        #pragma unroll
        for (int j = 0; j < 4; j++) {
            pqa = fmaf(vv[j],     rqa[j], pqa);
            pka = fmaf(vv[j],     rka[j], pka);
            pqb = fmaf(vv[4 + j], rqb[j], pqb);
            pkb = fmaf(vv[4 + j], rkb[j], pkb);
        }
        #pragma unroll
        for (int o = 8; o; o >>= 1) {
            pqa += __shfl_xor_sync(0xffffffffu, pqa, o);
            pka += __shfl_xor_sync(0xffffffffu, pka, o);
            pqb += __shfl_xor_sync(0xffffffffu, pqb, o);
            pkb += __shfl_xor_sync(0xffffffffu, pkb, o);
        }

        float n1 = 1.0f + (float)g_mask0[row] + (float)g_mask1[row] + (float)g_mask2[row];
        float wa = head_w(pqa, pka, n1);
        float wb = head_w(pqb, pkb, n1);

        float o8[8];
        float s1 = 0.f, s2 = 0.f;
        #pragma unroll
        for (int j = 0; j < 4; j++) {
            o8[j]     = fmaxf(vv[j] * wa, 0.f);
            o8[4 + j] = fmaxf(vv[4 + j] * wb, 0.f);
        }
        #pragma unroll
        for (int j = 0; j < 8; j++) { s1 += o8[j]; s2 = fmaf(o8[j], o8[j], s2); }
        #pragma unroll
        for (int o = 16; o; o >>= 1) {
            s1 += __shfl_xor_sync(0xffffffffu, s1, o);
            s2 += __shfl_xor_sync(0xffffffffu, s2, o);
        }
        float mu  = s1 * (1.0f / 256.0f);
        float var = s2 * (1.0f / 256.0f) - mu * mu;
        float rs  = rsqrtf(var + LN_EPS);

        float4 w0, w1;
        w0.x = (o8[0] - mu) * rs * ga[0] + ba[0];
        w0.y = (o8[1] - mu) * rs * ga[1] + ba[1];
        w0.z = (o8[2] - mu) * rs * ga[2] + ba[2];
        w0.w = (o8[3] - mu) * rs * ga[3] + ba[3];
        w1.x = (o8[4] - mu) * rs * gb[0] + bb[0];
        w1.y = (o8[5] - mu) * rs * gb[1] + bb[1];
        w1.z = (o8[6] - mu) * rs * gb[2] + bb[2];
        w1.w = (o8[7] - mu) * rs * gb[3] + bb[3];
        *(float4*)&out[(size_t)row * DIM + tx * 4]       = w0;
        *(float4*)&out[(size_t)row * DIM + 128 + tx * 4] = w1;
    }
}

// ---------------- launcher ----------------
extern "C" void kernel_launch(void* const* d_in, const int* in_sizes, int n_in,
                              void* d_out, int out_size)
{
    const float* feat  = (const float*)d_in[0];
    const float* Wr    = (const float*)d_in[3];
    const float* br    = (const float*)d_in[4];
    const float* rel_q = (const float*)d_in[7];
    const float* rel_k = (const float*)d_in[8];
    const float* ln_g  = (const float*)d_in[9];
    const float* ln_b  = (const float*)d_in[10];
    const int*   dst0  = (const int*)d_in[12];
    const int*   dst1  = (const int*)d_in[14];
    const int*   dst2  = (const int*)d_in[16];

    int n = in_sizes[0] / DIM;   // 50000
    int E = in_sizes[12];        // 400000

    static bool attr_set = false;
    const int smem_bytes = 64 * VS * sizeof(float);   // 67584
    if (!attr_set) {
        cudaFuncSetAttribute(mma_gemm_epilogue,
                             cudaFuncAttributeMaxDynamicSharedMemorySize, smem_bytes);
        attr_set = true;
    }

    convert_feat_kernel<<<(N_PAD * 32 + 255) / 256, 256>>>(feat, n);
    convert_w_kernel<<<(256 * 128 + 255) / 256, 256>>>(Wr);
    zero_mask_kernel<<<(n + 255) / 256, 256>>>(n);
    scatter_mask_kernel<<<(E + 255) / 256, 256>>>(dst0, dst1, dst2, E);

    int nb = (n + 63) / 64;      // 782
    mma_gemm_epilogue<<<nb, 256, smem_bytes>>>(
        br, rel_q, rel_k, ln_g, ln_b, (float*)d_out, n);
}

// round 3
// speedup vs baseline: 2.0130x; 2.0130x over previous
#include <cuda_runtime.h>
#include <cuda_bf16.h>
#include <cstdint>

#define N_NODES 50000
#define N_PAD   50048
#define DIM     256
#define NEG     0.2f
#define LN_EPS  1e-5f
#define BM      128
#define BK      32
#define THREADS 512

// SMEM layout (bytes), per stage: Ah[128][40]bf16, Al, Bh[256][40]bf16, Bl
#define AH_OFF  0
#define AL_OFF  10240
#define BH_OFF  20480
#define BL_OFF  40960
#define STAGE   61440
#define VS      264            // epilogue Vs row stride (floats)
#define SMEM_BYTES (BM * VS * 4)   // 135168 >= 2*STAGE

// ---------------- scratch ----------------
__device__ unsigned char g_mask[3 * N_PAD];        // 150144 bytes, 16B multiple
// Wr split hi/lo, packed [n][k2]: u32 = (bf16 k even, bf16 k odd)
__device__ uint32_t g_wh[256 * 128];
__device__ uint32_t g_wl[256 * 128];

// ---------------- helpers ----------------
__device__ __forceinline__ uint32_t pack_bf16(float a, float b) {
    __nv_bfloat162 h = __floats2bfloat162_rn(a, b);
    return *reinterpret_cast<uint32_t*>(&h);
}
__device__ __forceinline__ uint32_t s2u(const void* p) {
    return (uint32_t)__cvta_generic_to_shared(p);
}
__device__ __forceinline__ void ldmx4(uint32_t r[4], uint32_t addr) {
    asm volatile("ldmatrix.sync.aligned.m8n8.x4.shared.b16 {%0,%1,%2,%3}, [%4];"
                 : "=r"(r[0]), "=r"(r[1]), "=r"(r[2]), "=r"(r[3]) : "r"(addr));
}
__device__ __forceinline__ void ldmx2(uint32_t r[2], uint32_t addr) {
    asm volatile("ldmatrix.sync.aligned.m8n8.x2.shared.b16 {%0,%1}, [%2];"
                 : "=r"(r[0]), "=r"(r[1]) : "r"(addr));
}
__device__ __forceinline__ void cpasync16(uint32_t dst, const void* src) {
    asm volatile("cp.async.cg.shared.global [%0], [%1], 16;"
                 :: "r"(dst), "l"(src));
}
__device__ __forceinline__ void cpcommit() {
    asm volatile("cp.async.commit_group;");
}
__device__ __forceinline__ void cpwait0() {
    asm volatile("cp.async.wait_group 0;");
}
__device__ __forceinline__ void mma16816(float c[4], const uint32_t a[4],
                                         uint32_t b0, uint32_t b1) {
    asm volatile(
        "mma.sync.aligned.m16n8k16.row.col.f32.bf16.bf16.f32 "
        "{%0,%1,%2,%3}, {%4,%5,%6,%7}, {%8,%9}, {%0,%1,%2,%3};"
        : "+f"(c[0]), "+f"(c[1]), "+f"(c[2]), "+f"(c[3])
        : "r"(a[0]), "r"(a[1]), "r"(a[2]), "r"(a[3]), "r"(b0), "r"(b1));
}
__device__ __forceinline__ float head_w(float q, float kv, float n1) {
    float x1 = q + kv;
    float z1 = fmaxf(x1, NEG * x1);
    float z0 = fmaxf(q,  NEG * q);
    float m  = fmaxf(z1, z0);
    float e1 = expf(z1 - m);
    float e0 = expf(z0 - m);
    float f1 = n1 * e1;
    return f1 / (f1 + (4.0f - n1) * e0);
}

// ---------------- prep kernels ----------------
// convert Wr -> g_wh/g_wl, and zero masks (ordering before scatter via stream)
__global__ void convert_w_kernel(const float* __restrict__ Wr) {
    int idx = blockIdx.x * blockDim.x + threadIdx.x;   // 32768 threads
    // zero masks with uint4: 150144/16 = 9384 stores
    if (idx < 9384) *(uint4*)&g_mask[idx * 16] = make_uint4(0, 0, 0, 0);
    if (idx >= 256 * 128) return;
    int nn = idx >> 7;
    int k2 = idx & 127;
    float x0 = Wr[(size_t)(2 * k2)     * 256 + nn];
    float x1 = Wr[(size_t)(2 * k2 + 1) * 256 + nn];
    __nv_bfloat16 h0 = __float2bfloat16_rn(x0);
    __nv_bfloat16 h1 = __float2bfloat16_rn(x1);
    g_wh[idx] = pack_bf16(__bfloat162float(h0), __bfloat162float(h1));
    g_wl[idx] = pack_bf16(x0 - __bfloat162float(h0), x1 - __bfloat162float(h1));
}

__global__ void scatter_mask_kernel(const int* __restrict__ d0,
                                    const int* __restrict__ d1,
                                    const int* __restrict__ d2, int E4) {
    int i = blockIdx.x * blockDim.x + threadIdx.x;   // E/4 threads
    if (i >= E4) return;
    int4 a = ((const int4*)d0)[i];
    int4 b = ((const int4*)d1)[i];
    int4 c = ((const int4*)d2)[i];
    g_mask[a.x] = 1; g_mask[a.y] = 1; g_mask[a.z] = 1; g_mask[a.w] = 1;
    g_mask[N_PAD + b.x] = 1; g_mask[N_PAD + b.y] = 1;
    g_mask[N_PAD + b.z] = 1; g_mask[N_PAD + b.w] = 1;
    g_mask[2 * N_PAD + c.x] = 1; g_mask[2 * N_PAD + c.y] = 1;
    g_mask[2 * N_PAD + c.z] = 1; g_mask[2 * N_PAD + c.w] = 1;
}

// ---------------- fused GEMM (SMEM-staged HMMA, bf16x3) + epilogue ----------------
// 512 threads = 16 warps (4 m-groups x 4 n-groups). Warp tile 32x64.
__global__ __launch_bounds__(THREADS)
void mma_gemm_epilogue(const float* __restrict__ feat,
                       const float* __restrict__ br,
                       const float* __restrict__ rel_q,
                       const float* __restrict__ rel_k,
                       const float* __restrict__ ln_g,
                       const float* __restrict__ ln_b,
                       float* __restrict__ out, int n)
{
    extern __shared__ char smem[];
    const uint32_t smem_u = s2u(smem);

    const int tid  = threadIdx.x;
    const int wid  = tid >> 5;
    const int lane = tid & 31;
    const int wm   = wid & 3;       // m group: rows wm*32..+31
    const int wn   = wid >> 2;      // n group: cols wn*64..+63
    const int row0 = blockIdx.x * BM;

    float acc[2][8][4];
    #pragma unroll
    for (int mt = 0; mt < 2; mt++)
        #pragma unroll
        for (int nt = 0; nt < 8; nt++)
            #pragma unroll
            for (int q = 0; q < 4; q++) acc[mt][nt][q] = 0.0f;

    // ldmatrix lane address components
    const int l7  = lane & 7;
    const int q01 = (lane >> 3) & 1;
    const int q23 = lane >> 4;
    uint32_t arow[2];
    #pragma unroll
    for (int mt = 0; mt < 2; mt++)
        arow[mt] = (uint32_t)((wm * 32 + mt * 16 + q01 * 8 + l7) * 80);
    const uint32_t brow = (uint32_t)((wn * 64 + l7) * 80);   // + nt*8*80
    const uint32_t bgr  = (uint32_t)(q01 * 16);              // + ks*32

    // ---- A/B load lambdas (manually inlined) ----
    // A: thread loads 2 float4 of feat per chunk
    const int arow_l[2] = { (tid + 0)   >> 3, (tid + 512) >> 3 };
    const int acol_l[2] = { (tid + 0)   & 7,  (tid + 512) & 7  };
    // B: thread issues 2 hi + 2 lo cp.async per chunk
    const int bn_l[2] = { (tid + 0) >> 2, (tid + 512) >> 2 };
    const int bc_l[2] = { (tid + 0) & 3,  (tid + 512) & 3  };

    float4 areg[2];

    // ---- prologue: chunk 0 ----
    {
        #pragma unroll
        for (int w = 0; w < 2; w++) {
            int gr = row0 + arow_l[w]; if (gr >= n) gr = n - 1;
            areg[w] = *(const float4*)&feat[(size_t)gr * 256 + acol_l[w] * 4];
        }
        #pragma unroll
        for (int w = 0; w < 2; w++) {
            cpasync16(smem_u + BH_OFF + bn_l[w] * 80 + bc_l[w] * 16,
                      g_wh + bn_l[w] * 128 + bc_l[w] * 4);
            cpasync16(smem_u + BL_OFF + bn_l[w] * 80 + bc_l[w] * 16,
                      g_wl + bn_l[w] * 128 + bc_l[w] * 4);
        }
        cpcommit();
        #pragma unroll
        for (int w = 0; w < 2; w++) {
            float x[4] = {areg[w].x, areg[w].y, areg[w].z, areg[w].w};
            uint2 hi, lo;
            __nv_bfloat16 h0 = __float2bfloat16_rn(x[0]);
            __nv_bfloat16 h1 = __float2bfloat16_rn(x[1]);
            __nv_bfloat16 h2 = __float2bfloat16_rn(x[2]);
            __nv_bfloat16 h3 = __float2bfloat16_rn(x[3]);
            hi.x = pack_bf16(__bfloat162float(h0), __bfloat162float(h1));
            hi.y = pack_bf16(__bfloat162float(h2), __bfloat162float(h3));
            lo.x = pack_bf16(x[0] - __bfloat162float(h0), x[1] - __bfloat162float(h1));
            lo.y = pack_bf16(x[2] - __bfloat162float(h2), x[3] - __bfloat162float(h3));
            uint32_t off = arow_l[w] * 80 + (acol_l[w] >> 1) * 16 + (acol_l[w] & 1) * 8;
            *(uint2*)(smem + AH_OFF + off) = hi;
            *(uint2*)(smem + AL_OFF + off) = lo;
        }
    }

    // ---- main loop over 8 K-chunks ----
    for (int c = 0; c < 8; c++) {
        const uint32_t sb = smem_u + (uint32_t)(c & 1) * STAGE;
        cpwait0();
        __syncthreads();

        const int cn = c + 1;
        const uint32_t sn = smem_u + (uint32_t)(cn & 1) * STAGE;
        if (cn < 8) {
            #pragma unroll
            for (int w = 0; w < 2; w++) {
                int gr = row0 + arow_l[w]; if (gr >= n) gr = n - 1;
                areg[w] = *(const float4*)&feat[(size_t)gr * 256 + cn * 32 + acol_l[w] * 4];
            }
            #pragma unroll
            for (int w = 0; w < 2; w++) {
                cpasync16(sn + BH_OFF + bn_l[w] * 80 + bc_l[w] * 16,
                          g_wh + bn_l[w] * 128 + cn * 16 + bc_l[w] * 4);
                cpasync16(sn + BL_OFF + bn_l[w] * 80 + bc_l[w] * 16,
                          g_wl + bn_l[w] * 128 + cn * 16 + bc_l[w] * 4);
            }
            cpcommit();
        }

        // compute chunk c
        #pragma unroll
        for (int ks = 0; ks < 2; ks++) {
            uint32_t ah[2][4], al[2][4];
            #pragma unroll
            for (int mt = 0; mt < 2; mt++) {
                uint32_t aoff = arow[mt] + (uint32_t)(ks * 2 + q23) * 16;
                ldmx4(ah[mt], sb + AH_OFF + aoff);
                ldmx4(al[mt], sb + AL_OFF + aoff);
            }
            #pragma unroll
            for (int nt = 0; nt < 8; nt++) {
                uint32_t baddr = sb + BH_OFF + brow + (uint32_t)(nt * 640) +
                                 bgr + (uint32_t)(ks * 32);
                uint32_t bh[2], bl[2];
                ldmx2(bh, baddr);
                ldmx2(bl, baddr + (BL_OFF - BH_OFF));
                #pragma unroll
                for (int mt = 0; mt < 2; mt++) {
                    mma16816(acc[mt][nt], ah[mt], bh[0], bh[1]);
                    mma16816(acc[mt][nt], ah[mt], bl[0], bl[1]);
                    mma16816(acc[mt][nt], al[mt], bh[0], bh[1]);
                }
            }
        }

        if (cn < 8) {
            const char* dst = smem + (size_t)((cn & 1) * STAGE);
            #pragma unroll
            for (int w = 0; w < 2; w++) {
                float x[4] = {areg[w].x, areg[w].y, areg[w].z, areg[w].w};
                uint2 hi, lo;
                __nv_bfloat16 h0 = __float2bfloat16_rn(x[0]);
                __nv_bfloat16 h1 = __float2bfloat16_rn(x[1]);
                __nv_bfloat16 h2 = __float2bfloat16_rn(x[2]);
                __nv_bfloat16 h3 = __float2bfloat16_rn(x[3]);
                hi.x = pack_bf16(__bfloat162float(h0), __bfloat162float(h1));
                hi.y = pack_bf16(__bfloat162float(h2), __bfloat162float(h3));
                lo.x = pack_bf16(x[0] - __bfloat162float(h0), x[1] - __bfloat162float(h1));
                lo.y = pack_bf16(x[2] - __bfloat162float(h2), x[3] - __bfloat162float(h3));
                uint32_t off = arow_l[w] * 80 + (acol_l[w] >> 1) * 16 + (acol_l[w] & 1) * 8;
                *(uint2*)(const_cast<char*>(dst) + AH_OFF + off) = hi;
                *(uint2*)(const_cast<char*>(dst) + AL_OFF + off) = lo;
            }
        }
    }

    // ---- stage v tile to SMEM (reuses stage buffers) ----
    __syncthreads();
    float* Vs = (float*)smem;
    {
        const int rg = lane >> 2;      // 0..7
        const int cq = (lane & 3) * 2; // 0,2,4,6
        #pragma unroll
        for (int mt = 0; mt < 2; mt++) {
            #pragma unroll
            for (int nt = 0; nt < 8; nt++) {
                int r = wm * 32 + mt * 16 + rg;
                int cc = wn * 64 + nt * 8 + cq;
                Vs[r * VS + cc]           = acc[mt][nt][0];
                Vs[r * VS + cc + 1]       = acc[mt][nt][1];
                Vs[(r + 8) * VS + cc]     = acc[mt][nt][2];
                Vs[(r + 8) * VS + cc + 1] = acc[mt][nt][3];
            }
        }
    }
    __syncthreads();

    // ---- epilogue: metapath attention + ReLU + LayerNorm ----
    const int tx = lane;
    const int ci = (tx & 15) * 4;
    const int ha = tx >> 4;
    const int hb = 2 + (tx >> 4);
    float rqa[4], rka[4], rqb[4], rkb[4];
    float bra[4], brb[4], ga[4], gb[4], ba[4], bb[4];
    #pragma unroll
    for (int j = 0; j < 4; j++) {
        rqa[j] = rel_q[ha * 64 + ci + j];
        rka[j] = rel_k[ha * 64 + ci + j];
        rqb[j] = rel_q[hb * 64 + ci + j];
        rkb[j] = rel_k[hb * 64 + ci + j];
        int colA = tx * 4 + j;
        int colB = 128 + tx * 4 + j;
        bra[j] = br[colA];   brb[j] = br[colB];
        ga[j]  = ln_g[colA]; gb[j]  = ln_g[colB];
        ba[j]  = ln_b[colA]; bb[j]  = ln_b[colB];
    }

    #pragma unroll
    for (int i = 0; i < 8; i++) {
        int lrow = wid * 8 + i;
        int row  = row0 + lrow;
        if (row >= n) continue;

        float4 va = *(float4*)&Vs[lrow * VS + tx * 4];
        float4 vb = *(float4*)&Vs[lrow * VS + 128 + tx * 4];
        float vv[8];
        vv[0] = va.x + bra[0]; vv[1] = va.y + bra[1];
        vv[2] = va.z + bra[2]; vv[3] = va.w + bra[3];
        vv[4] = vb.x + brb[0]; vv[5] = vb.y + brb[1];
        vv[6] = vb.z + brb[2]; vv[7] = vb.w + brb[3];

        float pqa = 0.f, pka = 0.f, pqb = 0.f, pkb = 0.f;
        #pragma unroll
        for (int j = 0; j < 4; j++) {
            pqa = fmaf(vv[j],     rqa[j], pqa);
            pka = fmaf(vv[j],     rka[j], pka);
            pqb = fmaf(vv[4 + j], rqb[j], pqb);
            pkb = fmaf(vv[4 + j], rkb[j], pkb);
        }
        #pragma unroll
        for (int o = 8; o; o >>= 1) {
            pqa += __shfl_xor_sync(0xffffffffu, pqa, o);
            pka += __shfl_xor_sync(0xffffffffu, pka, o);
            pqb += __shfl_xor_sync(0xffffffffu, pqb, o);
            pkb += __shfl_xor_sync(0xffffffffu, pkb, o);
        }

        float n1 = 1.0f + (float)g_mask[row] + (float)g_mask[N_PAD + row]
                        + (float)g_mask[2 * N_PAD + row];
        float wa = head_w(pqa, pka, n1);
        float wb = head_w(pqb, pkb, n1);

        float o8[8];
        float s1 = 0.f, s2 = 0.f;
        #pragma unroll
        for (int j = 0; j < 4; j++) {
            o8[j]     = fmaxf(vv[j] * wa, 0.f);
            o8[4 + j] = fmaxf(vv[4 + j] * wb, 0.f);
        }
        #pragma unroll
        for (int j = 0; j < 8; j++) { s1 += o8[j]; s2 = fmaf(o8[j], o8[j], s2); }
        #pragma unroll
        for (int o = 16; o; o >>= 1) {
            s1 += __shfl_xor_sync(0xffffffffu, s1, o);
            s2 += __shfl_xor_sync(0xffffffffu, s2, o);
        }
        float mu  = s1 * (1.0f / 256.0f);
        float var = s2 * (1.0f / 256.0f) - mu * mu;
        float rs  = rsqrtf(var + LN_EPS);

        float4 w0, w1;
        w0.x = (o8[0] - mu) * rs * ga[0] + ba[0];
        w0.y = (o8[1] - mu) * rs * ga[1] + ba[1];
        w0.z = (o8[2] - mu) * rs * ga[2] + ba[2];
        w0.w = (o8[3] - mu) * rs * ga[3] + ba[3];
        w1.x = (o8[4] - mu) * rs * gb[0] + bb[0];
        w1.y = (o8[5] - mu) * rs * gb[1] + bb[1];
        w1.z = (o8[6] - mu) * rs * gb[2] + bb[2];
        w1.w = (o8[7] - mu) * rs * gb[3] + bb[3];
        *(float4*)&out[(size_t)row * DIM + tx * 4]       = w0;
        *(float4*)&out[(size_t)row * DIM + 128 + tx * 4] = w1;
    }
}

// ---------------- launcher ----------------
extern "C" void kernel_launch(void* const* d_in, const int* in_sizes, int n_in,
                              void* d_out, int out_size)
{
    const float* feat  = (const float*)d_in[0];
    const float* Wr    = (const float*)d_in[3];
    const float* br    = (const float*)d_in[4];
    const float* rel_q = (const float*)d_in[7];
    const float* rel_k = (const float*)d_in[8];
    const float* ln_g  = (const float*)d_in[9];
    const float* ln_b  = (const float*)d_in[10];
    const int*   dst0  = (const int*)d_in[12];
    const int*   dst1  = (const int*)d_in[14];
    const int*   dst2  = (const int*)d_in[16];

    int n = in_sizes[0] / DIM;   // 50000
    int E = in_sizes[12];        // 400000

    static bool attr_set = false;
    if (!attr_set) {
        cudaFuncSetAttribute(mma_gemm_epilogue,
                             cudaFuncAttributeMaxDynamicSharedMemorySize, SMEM_BYTES);
        attr_set = true;
    }

    convert_w_kernel<<<128, 256>>>(Wr);                  // also zeros masks
    int E4 = E / 4;
    scatter_mask_kernel<<<(E4 + 255) / 256, 256>>>(dst0, dst1, dst2, E4);

    int nb = (n + BM - 1) / BM;  // 391
    mma_gemm_epilogue<<<nb, THREADS, SMEM_BYTES>>>(
        feat, br, rel_q, rel_k, ln_g, ln_b, (float*)d_out, n);
}